// round 13
// baseline (speedup 1.0000x reference)
#include <cuda_runtime.h>
#include <cuda_bf16.h>
#include <math_constants.h>
#include <cstdint>

// ============================================================================
// Head: single-head causal attention. B=8, T=4096, C=768, D=64, fp32.
// Round 12: (1) complementary CTA->(b,qt) mapping so co-resident CTA pairs
// (bid, bid+148) have constant total work; (2) proj emits bf16 hi/lo directly
// (split2 out of attn hot loop; fills are pure copies; Q frags from global);
// (3) launch_bounds(256,2) pins 2 CTAs/SM.
// Tensor path: mma.sync.m16n8k16 bf16x3, no-max base-2 softmax, O in regs.
// ============================================================================

#define B_   8
#define T_   4096
#define C_   768
#define D_   64
#define BT_  (B_ * T_)
#define QSC  0.18033688011112042591f   // (1/sqrt(64)) * log2(e)

#define TQ 128      // queries per CTA
#define TK 128      // keys per kv tile
#define PITCH 72    // halves per smem row (144 B = 9 x 16 B, ldmatrix conflict-free)

typedef unsigned long long u64;

// ---------------- scratch (static, no allocations) ----------------
// bf16 hi/lo word arrays: [row][32 words] (word = 2 halves). 6 x 4 MB.
__device__ __align__(16) uint32_t g_qh[BT_ * 32], g_ql[BT_ * 32];
__device__ __align__(16) uint32_t g_kh[BT_ * 32], g_kl[BT_ * 32];
__device__ __align__(16) uint32_t g_vh[BT_ * 32], g_vl[BT_ * 32];

// ---------------- helpers ----------------
__device__ __forceinline__ uint32_t smem_u32(const void* p) {
    uint32_t a;
    asm("{ .reg .u64 t; cvta.to.shared.u64 t, %1; cvt.u32.u64 %0, t; }"
        : "=r"(a) : "l"(p));
    return a;
}
__device__ __forceinline__ float ex2(float x) {
    float r; asm("ex2.approx.f32 %0, %1;" : "=f"(r) : "f"(x)); return r;
}
__device__ __forceinline__ u64 pk2(float lo, float hi) {
    u64 r; asm("mov.b64 %0, {%1, %2};" : "=l"(r) : "f"(lo), "f"(hi)); return r;
}
__device__ __forceinline__ void fma2(u64& d, u64 a, u64 b) {
    asm("fma.rn.f32x2 %0, %1, %2, %0;" : "+l"(d) : "l"(a), "l"(b));
}
__device__ __forceinline__ float sum2(u64 v) {
    float lo, hi;
    asm("mov.b64 {%0, %1}, %2;" : "=f"(lo), "=f"(hi) : "l"(v));
    return lo + hi;
}
// fp32 pair -> bf16 hi pair + bf16 residual pair (packed words).
__device__ __forceinline__ void split2(float a, float b, uint32_t& hi, uint32_t& lo) {
    __nv_bfloat162 h = __floats2bfloat162_rn(a, b);
    float2 hf = __bfloat1622float2(h);
    __nv_bfloat162 l2 = __floats2bfloat162_rn(a - hf.x, b - hf.y);
    hi = *(uint32_t*)&h;
    lo = *(uint32_t*)&l2;
}
__device__ __forceinline__ void ldsm_x4(uint32_t* r, uint32_t addr) {
    asm volatile("ldmatrix.sync.aligned.m8n8.x4.shared.b16 {%0,%1,%2,%3}, [%4];"
                 : "=r"(r[0]), "=r"(r[1]), "=r"(r[2]), "=r"(r[3]) : "r"(addr));
}
__device__ __forceinline__ void ldsm_x4_t(uint32_t* r, uint32_t addr) {
    asm volatile("ldmatrix.sync.aligned.m8n8.x4.trans.shared.b16 {%0,%1,%2,%3}, [%4];"
                 : "=r"(r[0]), "=r"(r[1]), "=r"(r[2]), "=r"(r[3]) : "r"(addr));
}
__device__ __forceinline__ void mma16816(float* c, const uint32_t* a,
                                         uint32_t b0, uint32_t b1) {
    asm volatile(
        "mma.sync.aligned.m16n8k16.row.col.f32.bf16.bf16.f32 "
        "{%0,%1,%2,%3}, {%4,%5,%6,%7}, {%8,%9}, {%0,%1,%2,%3};"
        : "+f"(c[0]), "+f"(c[1]), "+f"(c[2]), "+f"(c[3])
        : "r"(a[0]), "r"(a[1]), "r"(a[2]), "r"(a[3]), "r"(b0), "r"(b1));
}

// ============================================================================
// Kernel 1: projection (FFMA2, measured). Outputs bf16 hi/lo word arrays.
// Q pre-scaled by QSC.
// ============================================================================
#define FMA_BLOCK(ACC, A0, A1, A2, A3, BA, BB)                                 \
    fma2(ACC[0][0], A0, BA.x); fma2(ACC[0][1], A0, BA.y);                      \
    fma2(ACC[0][2], A0, BB.x); fma2(ACC[0][3], A0, BB.y);                      \
    fma2(ACC[1][0], A1, BA.x); fma2(ACC[1][1], A1, BA.y);                      \
    fma2(ACC[1][2], A1, BB.x); fma2(ACC[1][3], A1, BB.y);                      \
    fma2(ACC[2][0], A2, BA.x); fma2(ACC[2][1], A2, BA.y);                      \
    fma2(ACC[2][2], A2, BB.x); fma2(ACC[2][3], A2, BB.y);                      \
    fma2(ACC[3][0], A3, BA.x); fma2(ACC[3][1], A3, BA.y);                      \
    fma2(ACC[3][2], A3, BB.x); fma2(ACC[3][3], A3, BB.y);

__global__ void __launch_bounds__(256)
proj_kernel(const float* __restrict__ x,
            const float* __restrict__ Wk,
            const float* __restrict__ Wq,
            const float* __restrict__ Wv) {
    __shared__ __align__(16) float xs[64 * 68];
    __shared__ __align__(16) u64   ws2[32 * 66];

    const int wy   = blockIdx.y;
    const float* W = (wy == 0) ? Wk : ((wy == 1) ? Wq : Wv);
    uint32_t* oh   = (wy == 0) ? g_kh : ((wy == 1) ? g_qh : g_vh);
    uint32_t* ol   = (wy == 0) ? g_kl : ((wy == 1) ? g_ql : g_vl);
    const float sc = (wy == 1) ? QSC : 1.0f;

    const int row0 = blockIdx.x * 64;
    const int tid  = threadIdx.x;
    const int tr4  = (tid >> 4) * 4;
    const int c0   = (tid & 15) * 2;   // owned cols: c0, c0+1, c0+32, c0+33

    u64 acc[4][4];
#pragma unroll
    for (int i = 0; i < 4; i++)
#pragma unroll
        for (int j = 0; j < 4; j++) acc[i][j] = 0ull;

    for (int kc = 0; kc < C_; kc += 64) {
#pragma unroll
        for (int i = 0; i < 4; i++) {
            int slot = i * 256 + tid;
            int r = slot >> 4;
            int c = (slot & 15) * 4;
            *(float4*)&xs[r * 68 + c] =
                *(const float4*)&x[(size_t)(row0 + r) * C_ + kc + c];
        }
#pragma unroll
        for (int i = 0; i < 2; i++) {
            int sp = i * 256 + tid;
            int kp = sp >> 4;
            int c  = (sp & 15) * 4;
            const float* wr = &W[(size_t)(kc + 2 * kp) * D_ + c];
            float4 wA = *(const float4*)wr;
            float4 wB = *(const float4*)(wr + D_);
            ulonglong2 p0 = { pk2(wA.x, wB.x), pk2(wA.y, wB.y) };
            ulonglong2 p1 = { pk2(wA.z, wB.z), pk2(wA.w, wB.w) };
            *(ulonglong2*)&ws2[kp * 66 + c]     = p0;
            *(ulonglong2*)&ws2[kp * 66 + c + 2] = p1;
        }
        __syncthreads();

#pragma unroll 4
        for (int kp2 = 0; kp2 < 16; kp2++) {
            const int fc = 4 * kp2;
            ulonglong2 a0 = *(const ulonglong2*)&xs[(tr4 + 0) * 68 + fc];
            ulonglong2 a1 = *(const ulonglong2*)&xs[(tr4 + 1) * 68 + fc];
            ulonglong2 a2 = *(const ulonglong2*)&xs[(tr4 + 2) * 68 + fc];
            ulonglong2 a3 = *(const ulonglong2*)&xs[(tr4 + 3) * 68 + fc];
            ulonglong2 bA0 = *(const ulonglong2*)&ws2[(2 * kp2) * 66 + c0];
            ulonglong2 bB0 = *(const ulonglong2*)&ws2[(2 * kp2) * 66 + 32 + c0];
            ulonglong2 bA1 = *(const ulonglong2*)&ws2[(2 * kp2 + 1) * 66 + c0];
            ulonglong2 bB1 = *(const ulonglong2*)&ws2[(2 * kp2 + 1) * 66 + 32 + c0];
            FMA_BLOCK(acc, a0.x, a1.x, a2.x, a3.x, bA0, bB0)
            FMA_BLOCK(acc, a0.y, a1.y, a2.y, a3.y, bA1, bB1)
        }
        __syncthreads();
    }

    // Epilogue: split to bf16 hi/lo words. Owned col pairs are word c0/2 and
    // word 16 + c0/2 of the 32-word row.
#pragma unroll
    for (int i = 0; i < 4; i++) {
        const size_t rw = (size_t)(row0 + tr4 + i) * 32;
        float v0 = sum2(acc[i][0]) * sc;
        float v1 = sum2(acc[i][1]) * sc;
        float v2 = sum2(acc[i][2]) * sc;
        float v3 = sum2(acc[i][3]) * sc;
        uint32_t h01, l01, h23, l23;
        split2(v0, v1, h01, l01);
        split2(v2, v3, h23, l23);
        oh[rw + (c0 >> 1)]      = h01;
        ol[rw + (c0 >> 1)]      = l01;
        oh[rw + 16 + (c0 >> 1)] = h23;
        ol[rw + 16 + (c0 >> 1)] = l23;
    }
}

// ============================================================================
// Kernel 2: mma.sync flash attention (bf16x3, no-max softmax).
// grid = 256, block = 256 (8 warps x 16 query rows), 2 CTAs/SM.
// smem: Khi | Klo | Vhi | Vlo, each [128 rows][PITCH halves].
// ============================================================================
#define SM_KHI  0
#define SM_KLO  18432
#define SM_VHI  36864
#define SM_VLO  55296
#define SM_ATTN 73728

__global__ void __launch_bounds__(256, 2)
attn_mma(float* __restrict__ out) {
    extern __shared__ __align__(16) char sm[];
    const uint32_t smb = smem_u32(sm);

    const int tid  = threadIdx.x;
    const int lane = tid & 31;
    const int wid  = tid >> 5;
    const int bid  = blockIdx.x;

    // ---- complementary work mapping: co-resident pair (bid, bid+148) has
    // constant total load; singleton SMs (bids 108..147) take the heaviest.
    int qt, b;
    if (bid >= 108 && bid < 148) {
        int k = bid - 108;                 // 0..39
        qt = 31 - (k >> 3);                // 31..27
        b  = k & 7;
    } else if (bid < 108) {
        qt = 26 - (bid >> 2);              // 26..0, 4 each
        b  = bid & 3;                      // batches 0..3
    } else {
        int i = bid - 148;                 // 0..107
        qt = i >> 2;                       // 0..26, 4 each
        b  = 4 + (i & 3);                  // batches 4..7
    }
    const int q0 = qt * TQ;
    const int m0 = wid * 16;               // warp's query rows within tile

    // ---- Q fragments straight from global (m16n8k16 .row A lane map) ----
    const int lq = lane >> 2;              // 0..7
    const int lk = lane & 3;               // 0..3
    uint32_t qhi[4][4], qlo[4][4];
    {
        const size_t r0w = ((size_t)b * T_ + q0 + m0 + lq) * 32;
        const size_t r1w = r0w + 8 * 32;
#pragma unroll
        for (int kk = 0; kk < 4; kk++) {
            const int wbase = kk * 8 + lk;
            qhi[kk][0] = g_qh[r0w + wbase];
            qhi[kk][1] = g_qh[r1w + wbase];
            qhi[kk][2] = g_qh[r0w + wbase + 4];
            qhi[kk][3] = g_qh[r1w + wbase + 4];
            qlo[kk][0] = g_ql[r0w + wbase];
            qlo[kk][1] = g_ql[r1w + wbase];
            qlo[kk][2] = g_ql[r0w + wbase + 4];
            qlo[kk][3] = g_ql[r1w + wbase + 4];
        }
    }

    float o[8][4];
#pragma unroll
    for (int i = 0; i < 8; i++)
#pragma unroll
        for (int j = 0; j < 4; j++) o[i][j] = 0.0f;
    float lsum0 = 0.0f, lsum1 = 0.0f;

    const int lc2 = 2 * lk;                 // c-frag col pair within n8
    // ldmatrix lane-address components
    const int krow = (lane & 7) + ((lane >> 4) & 1) * 8;  // + ch*16
    const int kcol = ((lane >> 3) & 1) * 8;               // + kk*16
    const int vrow = (lane & 7) + ((lane >> 3) & 1) * 8;  // + ch*16
    const int vcol = (lane >> 4) * 8;                     // + dd*16

    // fill addressing: thread -> (row, half-row of 4 uint4)
    const int frow = tid >> 1;
    const int fq   = (tid & 1) * 4;         // uint4 index within 8-uint4 row
    const int fsb  = frow * (PITCH * 2) + fq * 16;   // smem byte offset

    for (int kt = 0; kt <= qt; kt++) {
        const int k0 = kt * TK;
        const bool diag = (kt == qt);

        // ---- fill K/V hi/lo tiles: pure 16-B copies, no conversion ----
        {
            const size_t gq4 = ((size_t)b * T_ + k0 + frow) * 8 + fq; // uint4 units
            const uint4* kh4 = (const uint4*)g_kh;
            const uint4* kl4 = (const uint4*)g_kl;
            const uint4* vh4 = (const uint4*)g_vh;
            const uint4* vl4 = (const uint4*)g_vl;
#pragma unroll
            for (int j = 0; j < 4; j++) {
                *(uint4*)(sm + SM_KHI + fsb + 16 * j) = kh4[gq4 + j];
                *(uint4*)(sm + SM_KLO + fsb + 16 * j) = kl4[gq4 + j];
                *(uint4*)(sm + SM_VHI + fsb + 16 * j) = vh4[gq4 + j];
                *(uint4*)(sm + SM_VLO + fsb + 16 * j) = vl4[gq4 + j];
            }
        }
        __syncthreads();

        for (int ch = 0; ch < 8; ch++) {
            if (diag && ch * 16 > m0 + 15) break;   // fully-masked chunks

            // ---- S chunk = Q(16xd) K^T(16 keys): bf16x3, 18 MMAs ----
            float scf[8];
#pragma unroll
            for (int i = 0; i < 8; i++) scf[i] = 0.0f;
            {
                const uint32_t kh = smb + SM_KHI +
                    (uint32_t)((ch * 16 + krow) * PITCH + kcol) * 2;
                const uint32_t kl = smb + SM_KLO +
                    (uint32_t)((ch * 16 + krow) * PITCH + kcol) * 2;
#pragma unroll
                for (int kk = 0; kk < 4; kk++) {
                    uint32_t bh[4], bl[4];
                    ldsm_x4(bh, kh + kk * 32);
                    ldsm_x4(bl, kl + kk * 32);
                    mma16816(scf,     qhi[kk], bh[0], bh[1]);
                    mma16816(scf + 4, qhi[kk], bh[2], bh[3]);
                    mma16816(scf,     qhi[kk], bl[0], bl[1]);
                    mma16816(scf + 4, qhi[kk], bl[2], bl[3]);
                    mma16816(scf,     qlo[kk], bh[0], bh[1]);
                    mma16816(scf + 4, qlo[kk], bh[2], bh[3]);
                }
            }

            // ---- softmax (no max): p = exp2(s), causal mask on diagonal ----
            const int kb   = ch * 16 + lc2;
            const int lim0 = diag ? (m0 + lq)     : (1 << 30);
            const int lim1 = diag ? (m0 + lq + 8) : (1 << 30);
            float p0 = (kb     <= lim0) ? ex2(scf[0]) : 0.0f;
            float p1 = (kb + 1 <= lim0) ? ex2(scf[1]) : 0.0f;
            float p2 = (kb     <= lim1) ? ex2(scf[2]) : 0.0f;
            float p3 = (kb + 1 <= lim1) ? ex2(scf[3]) : 0.0f;
            float p4 = (kb + 8 <= lim0) ? ex2(scf[4]) : 0.0f;
            float p5 = (kb + 9 <= lim0) ? ex2(scf[5]) : 0.0f;
            float p6 = (kb + 8 <= lim1) ? ex2(scf[6]) : 0.0f;
            float p7 = (kb + 9 <= lim1) ? ex2(scf[7]) : 0.0f;
            lsum0 += (p0 + p1) + (p4 + p5);
            lsum1 += (p2 + p3) + (p6 + p7);

            // C-frag -> A-frag repack (registers only)
            uint32_t phi[4], plo[4];
            split2(p0, p1, phi[0], plo[0]);
            split2(p2, p3, phi[1], plo[1]);
            split2(p4, p5, phi[2], plo[2]);
            split2(p6, p7, phi[3], plo[3]);

            // ---- O += P(16x16 keys) V(16 keys x 64): bf16x3, 24 MMAs ----
            {
                const uint32_t vh = smb + SM_VHI +
                    (uint32_t)((ch * 16 + vrow) * PITCH + vcol) * 2;
                const uint32_t vl = smb + SM_VLO +
                    (uint32_t)((ch * 16 + vrow) * PITCH + vcol) * 2;
#pragma unroll
                for (int dd = 0; dd < 4; dd++) {
                    uint32_t bh[4], bl[4];
                    ldsm_x4_t(bh, vh + dd * 32);
                    ldsm_x4_t(bl, vl + dd * 32);
                    mma16816(o[2 * dd],     phi, bh[0], bh[1]);
                    mma16816(o[2 * dd + 1], phi, bh[2], bh[3]);
                    mma16816(o[2 * dd],     phi, bl[0], bl[1]);
                    mma16816(o[2 * dd + 1], phi, bl[2], bl[3]);
                    mma16816(o[2 * dd],     plo, bh[0], bh[1]);
                    mma16816(o[2 * dd + 1], plo, bh[2], bh[3]);
                }
            }
        }
        __syncthreads();   // smem tiles reusable
    }

    // ---- epilogue: reduce l across the quad, normalize, store ----
    lsum0 += __shfl_xor_sync(0xffffffffu, lsum0, 1);
    lsum0 += __shfl_xor_sync(0xffffffffu, lsum0, 2);
    lsum1 += __shfl_xor_sync(0xffffffffu, lsum1, 1);
    lsum1 += __shfl_xor_sync(0xffffffffu, lsum1, 2);
    const float inv0 = 1.0f / lsum0;
    const float inv1 = 1.0f / lsum1;

    const size_t r0 = (size_t)b * T_ + q0 + m0 + lq;
    const size_t r1 = r0 + 8;
#pragma unroll
    for (int dd = 0; dd < 8; dd++) {
        float2 w0 = { o[dd][0] * inv0, o[dd][1] * inv0 };
        float2 w1 = { o[dd][2] * inv1, o[dd][3] * inv1 };
        *(float2*)&out[r0 * D_ + dd * 8 + lc2] = w0;
        *(float2*)&out[r1 * D_ + dd * 8 + lc2] = w1;
    }
}

// ============================================================================
extern "C" void kernel_launch(void* const* d_in, const int* in_sizes, int n_in,
                              void* d_out, int out_size) {
    const float* x  = (const float*)d_in[0];
    const float* Wk = (const float*)d_in[1];
    const float* Wq = (const float*)d_in[2];
    const float* Wv = (const float*)d_in[3];
    float* out = (float*)d_out;
    (void)in_sizes; (void)n_in; (void)out_size;

    cudaFuncSetAttribute(attn_mma,
                         cudaFuncAttributeMaxDynamicSharedMemorySize,
                         SM_ATTN);

    proj_kernel<<<dim3(BT_ / 64, 3), 256>>>(x, Wk, Wq, Wv);
    attn_mma<<<B_ * (T_ / TQ), 256, SM_ATTN>>>(out);
}

// round 16
// speedup vs baseline: 1.1625x; 1.1625x over previous
#include <cuda_runtime.h>
#include <cuda_bf16.h>
#include <math_constants.h>
#include <cstdint>

// ============================================================================
// Head: single-head causal attention. B=8, T=4096, C=768, D=64, fp32.
// Round 15 = Round 13 resubmit (two consecutive infra failures, kernel never
// ran). Projection on tensor cores (mma.sync bf16x3) using the exact
// fragment/lane machinery validated in the attention kernel. Attention
// unchanged from R12 (measured 314 us).
// ============================================================================

#define B_   8
#define T_   4096
#define C_   768
#define D_   64
#define BT_  (B_ * T_)
#define QSC  0.18033688011112042591f   // (1/sqrt(64)) * log2(e)

#define TQ 128      // queries per CTA
#define TK 128      // keys per kv tile
#define PITCH 72    // halves per smem row (144 B = 9 x 16 B, ldmatrix conflict-free)

typedef unsigned long long u64;

// ---------------- scratch (static, no allocations) ----------------
// bf16 hi/lo word arrays: [row][32 words] (word = 2 halves). 6 x 4 MB.
__device__ __align__(16) uint32_t g_qh[BT_ * 32], g_ql[BT_ * 32];
__device__ __align__(16) uint32_t g_kh[BT_ * 32], g_kl[BT_ * 32];
__device__ __align__(16) uint32_t g_vh[BT_ * 32], g_vl[BT_ * 32];

// ---------------- helpers ----------------
__device__ __forceinline__ uint32_t smem_u32(const void* p) {
    uint32_t a;
    asm("{ .reg .u64 t; cvta.to.shared.u64 t, %1; cvt.u32.u64 %0, t; }"
        : "=r"(a) : "l"(p));
    return a;
}
__device__ __forceinline__ float ex2(float x) {
    float r; asm("ex2.approx.f32 %0, %1;" : "=f"(r) : "f"(x)); return r;
}
// fp32 pair -> bf16 hi pair + bf16 residual pair (packed words).
__device__ __forceinline__ void split2(float a, float b, uint32_t& hi, uint32_t& lo) {
    __nv_bfloat162 h = __floats2bfloat162_rn(a, b);
    float2 hf = __bfloat1622float2(h);
    __nv_bfloat162 l2 = __floats2bfloat162_rn(a - hf.x, b - hf.y);
    hi = *(uint32_t*)&h;
    lo = *(uint32_t*)&l2;
}
__device__ __forceinline__ void ldsm_x4(uint32_t* r, uint32_t addr) {
    asm volatile("ldmatrix.sync.aligned.m8n8.x4.shared.b16 {%0,%1,%2,%3}, [%4];"
                 : "=r"(r[0]), "=r"(r[1]), "=r"(r[2]), "=r"(r[3]) : "r"(addr));
}
__device__ __forceinline__ void ldsm_x4_t(uint32_t* r, uint32_t addr) {
    asm volatile("ldmatrix.sync.aligned.m8n8.x4.trans.shared.b16 {%0,%1,%2,%3}, [%4];"
                 : "=r"(r[0]), "=r"(r[1]), "=r"(r[2]), "=r"(r[3]) : "r"(addr));
}
__device__ __forceinline__ void mma16816(float* c, const uint32_t* a,
                                         uint32_t b0, uint32_t b1) {
    asm volatile(
        "mma.sync.aligned.m16n8k16.row.col.f32.bf16.bf16.f32 "
        "{%0,%1,%2,%3}, {%4,%5,%6,%7}, {%8,%9}, {%0,%1,%2,%3};"
        : "+f"(c[0]), "+f"(c[1]), "+f"(c[2]), "+f"(c[3])
        : "r"(a[0]), "r"(a[1]), "r"(a[2]), "r"(a[3]), "r"(b0), "r"(b1));
}

// ============================================================================
// Kernel 1: projection on tensor cores (bf16x3).
// grid (256, 3): x = 128-row tile, y = {K, Q, V}. block 256 = 8 warps x 16 rows.
// Per 64-wide k-chunk: X[128][64] split to bf16 hi/lo smem (A via ldsm),
// W[64k][64n] staged naturally hi/lo (B via ldsm.trans, like V in attention).
// smem: Xhi | Xlo (18432 B each) | Whi | Wlo (9216 B each) = 55296 B.
// ============================================================================
#define PSM_XHI 0
#define PSM_XLO 18432
#define PSM_WHI 36864
#define PSM_WLO 46080
#define PSM_TOT 55296

__global__ void __launch_bounds__(256, 2)
proj_mma(const float* __restrict__ x,
         const float* __restrict__ Wk,
         const float* __restrict__ Wq,
         const float* __restrict__ Wv) {
    extern __shared__ __align__(16) char sm[];
    const uint32_t smb = smem_u32(sm);

    const int wy   = blockIdx.y;
    const float* W = (wy == 0) ? Wk : ((wy == 1) ? Wq : Wv);
    uint32_t* oh   = (wy == 0) ? g_kh : ((wy == 1) ? g_qh : g_vh);
    uint32_t* ol   = (wy == 0) ? g_kl : ((wy == 1) ? g_ql : g_vl);
    const float sc = (wy == 1) ? QSC : 1.0f;

    const int row0 = blockIdx.x * 128;
    const int tid  = threadIdx.x;
    const int lane = tid & 31;
    const int wid  = tid >> 5;
    const int m0   = wid * 16;

    // fragment lane-address components (identical maps to attention kernel)
    const int arow = m0 + (lane & 7) + ((lane >> 3) & 1) * 8;
    const int acol = ((lane >> 4) & 1) * 8;
    const int brow = (lane & 7) + ((lane >> 3) & 1) * 8;   // + kk*16
    const int bcol = (lane >> 4) * 8;                      // + dd*16
    const uint32_t xh_a = smb + PSM_XHI + (uint32_t)(arow * PITCH + acol) * 2;
    const uint32_t xl_a = smb + PSM_XLO + (uint32_t)(arow * PITCH + acol) * 2;

    float o[8][4];
#pragma unroll
    for (int i = 0; i < 8; i++)
#pragma unroll
        for (int j = 0; j < 4; j++) o[i][j] = 0.0f;

    for (int kc = 0; kc < C_; kc += 64) {
        // ---- fill X chunk: 128 x 64 fp32 -> bf16 hi/lo ----
        {
            const int row = tid >> 1;
            const int d0  = (tid & 1) * 32;
            const float* gp = x + (size_t)(row0 + row) * C_ + kc + d0;
            const int bo = (row * PITCH + d0) * 2;
#pragma unroll
            for (int j = 0; j < 8; j++) {
                float4 f = *(const float4*)(gp + 4 * j);
                uint32_t h0, l0, h1, l1;
                split2(f.x, f.y, h0, l0);
                split2(f.z, f.w, h1, l1);
                uint2 ph = { h0, h1 }, pl = { l0, l1 };
                *(uint2*)(sm + PSM_XHI + bo + 8 * j) = ph;
                *(uint2*)(sm + PSM_XLO + bo + 8 * j) = pl;
            }
        }
        // ---- fill W chunk: 64 x 64 fp32 -> bf16 hi/lo ([k][n] natural) ----
        {
            const int row = tid >> 2;
            const int d0  = (tid & 3) * 16;
            const float* gp = W + (size_t)(kc + row) * D_ + d0;
            const int bo = (row * PITCH + d0) * 2;
#pragma unroll
            for (int j = 0; j < 4; j++) {
                float4 f = *(const float4*)(gp + 4 * j);
                uint32_t h0, l0, h1, l1;
                split2(f.x, f.y, h0, l0);
                split2(f.z, f.w, h1, l1);
                uint2 ph = { h0, h1 }, pl = { l0, l1 };
                *(uint2*)(sm + PSM_WHI + bo + 8 * j) = ph;
                *(uint2*)(sm + PSM_WLO + bo + 8 * j) = pl;
            }
        }
        __syncthreads();

        // ---- 96 MMAs: out[m16][n64] += X[m16][k64] W[k64][n64], bf16x3 ----
#pragma unroll
        for (int kk = 0; kk < 4; kk++) {
            uint32_t ah[4], al[4];
            ldsm_x4(ah, xh_a + kk * 32);
            ldsm_x4(al, xl_a + kk * 32);
            const uint32_t wb = (uint32_t)((kk * 16 + brow) * PITCH + bcol) * 2;
#pragma unroll
            for (int dd = 0; dd < 4; dd++) {
                uint32_t bh[4], bl[4];
                ldsm_x4_t(bh, smb + PSM_WHI + wb + dd * 32);
                ldsm_x4_t(bl, smb + PSM_WLO + wb + dd * 32);
                mma16816(o[2 * dd],     ah, bh[0], bh[1]);
                mma16816(o[2 * dd + 1], ah, bh[2], bh[3]);
                mma16816(o[2 * dd],     ah, bl[0], bl[1]);
                mma16816(o[2 * dd + 1], ah, bl[2], bl[3]);
                mma16816(o[2 * dd],     al, bh[0], bh[1]);
                mma16816(o[2 * dd + 1], al, bh[2], bh[3]);
            }
        }
        __syncthreads();
    }

    // ---- epilogue: scale, split to hi/lo words, store ----
    const int lq = lane >> 2;
    const int lk = lane & 3;
    const size_t r0w = (size_t)(row0 + m0 + lq) * 32;
    const size_t r1w = r0w + 8 * 32;
#pragma unroll
    for (int i = 0; i < 8; i++) {
        uint32_t h, l;
        split2(o[i][0] * sc, o[i][1] * sc, h, l);
        oh[r0w + i * 4 + lk] = h;
        ol[r0w + i * 4 + lk] = l;
        split2(o[i][2] * sc, o[i][3] * sc, h, l);
        oh[r1w + i * 4 + lk] = h;
        ol[r1w + i * 4 + lk] = l;
    }
}

// ============================================================================
// Kernel 2: mma.sync flash attention (bf16x3, no-max softmax). UNCHANGED R12.
// grid = 256, block = 256 (8 warps x 16 query rows), 2 CTAs/SM.
// smem: Khi | Klo | Vhi | Vlo, each [128 rows][PITCH halves].
// ============================================================================
#define SM_KHI  0
#define SM_KLO  18432
#define SM_VHI  36864
#define SM_VLO  55296
#define SM_ATTN 73728

__global__ void __launch_bounds__(256, 2)
attn_mma(float* __restrict__ out) {
    extern __shared__ __align__(16) char sm[];
    const uint32_t smb = smem_u32(sm);

    const int tid  = threadIdx.x;
    const int lane = tid & 31;
    const int wid  = tid >> 5;
    const int bid  = blockIdx.x;

    // complementary work mapping: co-resident pair (bid, bid+148) has
    // constant total load; singleton SMs (bids 108..147) take the heaviest.
    int qt, b;
    if (bid >= 108 && bid < 148) {
        int k = bid - 108;                 // 0..39
        qt = 31 - (k >> 3);                // 31..27
        b  = k & 7;
    } else if (bid < 108) {
        qt = 26 - (bid >> 2);              // 26..0, 4 each
        b  = bid & 3;
    } else {
        int i = bid - 148;                 // 0..107
        qt = i >> 2;
        b  = 4 + (i & 3);
    }
    const int q0 = qt * TQ;
    const int m0 = wid * 16;

    // Q fragments straight from global (m16n8k16 .row A lane map)
    const int lq = lane >> 2;
    const int lk = lane & 3;
    uint32_t qhi[4][4], qlo[4][4];
    {
        const size_t r0w = ((size_t)b * T_ + q0 + m0 + lq) * 32;
        const size_t r1w = r0w + 8 * 32;
#pragma unroll
        for (int kk = 0; kk < 4; kk++) {
            const int wbase = kk * 8 + lk;
            qhi[kk][0] = g_qh[r0w + wbase];
            qhi[kk][1] = g_qh[r1w + wbase];
            qhi[kk][2] = g_qh[r0w + wbase + 4];
            qhi[kk][3] = g_qh[r1w + wbase + 4];
            qlo[kk][0] = g_ql[r0w + wbase];
            qlo[kk][1] = g_ql[r1w + wbase];
            qlo[kk][2] = g_ql[r0w + wbase + 4];
            qlo[kk][3] = g_ql[r1w + wbase + 4];
        }
    }

    float o[8][4];
#pragma unroll
    for (int i = 0; i < 8; i++)
#pragma unroll
        for (int j = 0; j < 4; j++) o[i][j] = 0.0f;
    float lsum0 = 0.0f, lsum1 = 0.0f;

    const int lc2 = 2 * lk;
    const int krow = (lane & 7) + ((lane >> 4) & 1) * 8;  // + ch*16
    const int kcol = ((lane >> 3) & 1) * 8;               // + kk*16
    const int vrow = (lane & 7) + ((lane >> 3) & 1) * 8;  // + ch*16
    const int vcol = (lane >> 4) * 8;                     // + dd*16

    const int frow = tid >> 1;
    const int fq   = (tid & 1) * 4;
    const int fsb  = frow * (PITCH * 2) + fq * 16;

    for (int kt = 0; kt <= qt; kt++) {
        const int k0 = kt * TK;
        const bool diag = (kt == qt);

        // fill K/V hi/lo tiles: pure 16-B copies
        {
            const size_t gq4 = ((size_t)b * T_ + k0 + frow) * 8 + fq;
            const uint4* kh4 = (const uint4*)g_kh;
            const uint4* kl4 = (const uint4*)g_kl;
            const uint4* vh4 = (const uint4*)g_vh;
            const uint4* vl4 = (const uint4*)g_vl;
#pragma unroll
            for (int j = 0; j < 4; j++) {
                *(uint4*)(sm + SM_KHI + fsb + 16 * j) = kh4[gq4 + j];
                *(uint4*)(sm + SM_KLO + fsb + 16 * j) = kl4[gq4 + j];
                *(uint4*)(sm + SM_VHI + fsb + 16 * j) = vh4[gq4 + j];
                *(uint4*)(sm + SM_VLO + fsb + 16 * j) = vl4[gq4 + j];
            }
        }
        __syncthreads();

        for (int ch = 0; ch < 8; ch++) {
            if (diag && ch * 16 > m0 + 15) break;

            // S chunk = Q(16xd) K^T(16 keys): bf16x3
            float scf[8];
#pragma unroll
            for (int i = 0; i < 8; i++) scf[i] = 0.0f;
            {
                const uint32_t kh = smb + SM_KHI +
                    (uint32_t)((ch * 16 + krow) * PITCH + kcol) * 2;
                const uint32_t kl = smb + SM_KLO +
                    (uint32_t)((ch * 16 + krow) * PITCH + kcol) * 2;
#pragma unroll
                for (int kk = 0; kk < 4; kk++) {
                    uint32_t bh[4], bl[4];
                    ldsm_x4(bh, kh + kk * 32);
                    ldsm_x4(bl, kl + kk * 32);
                    mma16816(scf,     qhi[kk], bh[0], bh[1]);
                    mma16816(scf + 4, qhi[kk], bh[2], bh[3]);
                    mma16816(scf,     qhi[kk], bl[0], bl[1]);
                    mma16816(scf + 4, qhi[kk], bl[2], bl[3]);
                    mma16816(scf,     qlo[kk], bh[0], bh[1]);
                    mma16816(scf + 4, qlo[kk], bh[2], bh[3]);
                }
            }

            // softmax (no max): p = exp2(s), causal mask on diagonal
            const int kb   = ch * 16 + lc2;
            const int lim0 = diag ? (m0 + lq)     : (1 << 30);
            const int lim1 = diag ? (m0 + lq + 8) : (1 << 30);
            float p0 = (kb     <= lim0) ? ex2(scf[0]) : 0.0f;
            float p1 = (kb + 1 <= lim0) ? ex2(scf[1]) : 0.0f;
            float p2 = (kb     <= lim1) ? ex2(scf[2]) : 0.0f;
            float p3 = (kb + 1 <= lim1) ? ex2(scf[3]) : 0.0f;
            float p4 = (kb + 8 <= lim0) ? ex2(scf[4]) : 0.0f;
            float p5 = (kb + 9 <= lim0) ? ex2(scf[5]) : 0.0f;
            float p6 = (kb + 8 <= lim1) ? ex2(scf[6]) : 0.0f;
            float p7 = (kb + 9 <= lim1) ? ex2(scf[7]) : 0.0f;
            lsum0 += (p0 + p1) + (p4 + p5);
            lsum1 += (p2 + p3) + (p6 + p7);

            uint32_t phi[4], plo[4];
            split2(p0, p1, phi[0], plo[0]);
            split2(p2, p3, phi[1], plo[1]);
            split2(p4, p5, phi[2], plo[2]);
            split2(p6, p7, phi[3], plo[3]);

            // O += P(16x16 keys) V(16 keys x 64): bf16x3
            {
                const uint32_t vh = smb + SM_VHI +
                    (uint32_t)((ch * 16 + vrow) * PITCH + vcol) * 2;
                const uint32_t vl = smb + SM_VLO +
                    (uint32_t)((ch * 16 + vrow) * PITCH + vcol) * 2;
#pragma unroll
                for (int dd = 0; dd < 4; dd++) {
                    uint32_t bh[4], bl[4];
                    ldsm_x4_t(bh, vh + dd * 32);
                    ldsm_x4_t(bl, vl + dd * 32);
                    mma16816(o[2 * dd],     phi, bh[0], bh[1]);
                    mma16816(o[2 * dd + 1], phi, bh[2], bh[3]);
                    mma16816(o[2 * dd],     phi, bl[0], bl[1]);
                    mma16816(o[2 * dd + 1], phi, bl[2], bl[3]);
                    mma16816(o[2 * dd],     plo, bh[0], bh[1]);
                    mma16816(o[2 * dd + 1], plo, bh[2], bh[3]);
                }
            }
        }
        __syncthreads();
    }

    // epilogue: reduce l across the quad, normalize, store
    lsum0 += __shfl_xor_sync(0xffffffffu, lsum0, 1);
    lsum0 += __shfl_xor_sync(0xffffffffu, lsum0, 2);
    lsum1 += __shfl_xor_sync(0xffffffffu, lsum1, 1);
    lsum1 += __shfl_xor_sync(0xffffffffu, lsum1, 2);
    const float inv0 = 1.0f / lsum0;
    const float inv1 = 1.0f / lsum1;

    const size_t r0 = (size_t)b * T_ + q0 + m0 + lq;
    const size_t r1 = r0 + 8;
#pragma unroll
    for (int dd = 0; dd < 8; dd++) {
        float2 w0 = { o[dd][0] * inv0, o[dd][1] * inv0 };
        float2 w1 = { o[dd][2] * inv1, o[dd][3] * inv1 };
        *(float2*)&out[r0 * D_ + dd * 8 + lc2] = w0;
        *(float2*)&out[r1 * D_ + dd * 8 + lc2] = w1;
    }
}

// ============================================================================
extern "C" void kernel_launch(void* const* d_in, const int* in_sizes, int n_in,
                              void* d_out, int out_size) {
    const float* x  = (const float*)d_in[0];
    const float* Wk = (const float*)d_in[1];
    const float* Wq = (const float*)d_in[2];
    const float* Wv = (const float*)d_in[3];
    float* out = (float*)d_out;
    (void)in_sizes; (void)n_in; (void)out_size;

    cudaFuncSetAttribute(proj_mma,
                         cudaFuncAttributeMaxDynamicSharedMemorySize,
                         PSM_TOT);
    cudaFuncSetAttribute(attn_mma,
                         cudaFuncAttributeMaxDynamicSharedMemorySize,
                         SM_ATTN);

    proj_mma<<<dim3(BT_ / 128, 3), 256, PSM_TOT>>>(x, Wk, Wq, Wv);
    attn_mma<<<B_ * (T_ / TQ), 256, SM_ATTN>>>(out);
}